// round 8
// baseline (speedup 1.0000x reference)
#include <cuda_runtime.h>
#include <cstdint>

#define Bsz 256
#define Tt  200
#define Dd  128
#define Hh  256
#define Oo  128
#define Mm  64
#define NTHR 256
#define KPAD 272           // 256 k's + 16 zero pad (gpre prefetch overrun)
#define BT  (Bsz*Tt)       // 51200
#define RPP 16             // bt-rows per G-precompute CTA
#define EROWS 32           // bt-rows per epilogue CTA

// ---- scan decomposition: 128 persistent CTAs = 8 row-groups x 16 h-groups ----
#define SCTA 128
#define STH  512
#define ROWS_PC 32         // batch rows per CTA
#define HC_PC   16         // h columns per CTA
#define HSTR 260           // hdup row stride in u64 (bank-conflict pad)

typedef unsigned long long u64;

// ---------------- device globals (no allocs allowed) ----------------
__device__ __align__(16) float4 g_A4 [KPAD * 256];   // [k][h] = (Ai,Af,Ao,Ac)[h][k], k indexes [z|zp]
__device__ __align__(16) float4 g_Bh4[KPAD * 256];   // [k][h] = (Bi,Bf,Bo,Bc)[h][k], k indexes h_prev
__device__ __align__(16) float4 g_bias4[256];        // folded gate biases
__device__ float  g_Wqh[64 * 256];                   // Wq_h = Wq[:,256:384] @ Wfc   [m][hc]
__device__ float  g_bqe[64];                         // bq + Wq[:,256:] @ bfc
__device__ __align__(8) float2 g_WfcT2[128 * 128];   // [hp][o] = (Wfc[o][2hp], Wfc[o][2hp+1])
__device__ float  g_wzd[128], g_wzpd[128];
__device__ __align__(16) float4 g_G4[(long)BT * 256];// 200 MB: precomputed A@[z,zp]+bias
__device__ float  g_H [(long)BT * 256];              // 50 MB: h_t for the epilogue
__device__ __align__(16) float g_Hex[2 * 8 * 16 * (ROWS_PC * HC_PC)];  // h exchange, [buf][rg][hg][row*16+hc]
__device__ int    g_flag[SCTA];                      // [rg*16+hg], reset each launch

// ---------------- helpers ----------------
__device__ __forceinline__ float fast_sigmoid(float x) { return 1.0f / (1.0f + __expf(-x)); }
__device__ __forceinline__ float fast_tanh(float x)    { return 1.0f - 2.0f / (__expf(2.0f * x) + 1.0f); }
__device__ __forceinline__ u64 pack2(float lo, float hi) {
    u64 r; asm("mov.b64 %0, {%1, %2};" : "=l"(r) : "f"(lo), "f"(hi)); return r;
}
__device__ __forceinline__ u64 dup2(float v) {
    u64 r; asm("mov.b64 %0, {%1, %1};" : "=l"(r) : "f"(v)); return r;
}
__device__ __forceinline__ void unpack2(u64 v, float& lo, float& hi) {
    asm("mov.b64 {%0, %1}, %2;" : "=f"(lo), "=f"(hi) : "l"(v));
}
__device__ __forceinline__ void fma2(u64& d, u64 a, u64 b) {
    asm("fma.rn.f32x2 %0, %1, %2, %0;" : "+l"(d) : "l"(a), "l"(b));
}
__device__ __forceinline__ u64 add2(u64 a, u64 b) {
    u64 r; asm("add.rn.f32x2 %0, %1, %2;" : "=l"(r) : "l"(a), "l"(b)); return r;
}
__device__ __forceinline__ ulonglong2 ldcg_v2(const ulonglong2* p) {
    ulonglong2 v;
    asm("ld.global.cg.v2.b64 {%0, %1}, [%2];" : "=l"(v.x), "=l"(v.y) : "l"(p));
    return v;
}

// ================= reset: flags + h exchange slot 1 (h_{-1} = 0), every launch =========
__global__ void reset_kernel()
{
    int i = blockIdx.x * blockDim.x + threadIdx.x;
    if (i < SCTA) g_flag[i] = 0;
    const int slot = 8 * 16 * (ROWS_PC * HC_PC);     // 65536 floats per buffer
    for (int e = i; e < slot; e += gridDim.x * blockDim.x)
        g_Hex[slot + e] = 0.0f;                       // slot 1 = h_prev for t=0
}

// ================= prep1: Wq_h = Wq_xi @ Wfc ; bq_eff =================
__global__ void prep1_kernel(const float* __restrict__ Wq, const float* __restrict__ Wfc,
                             const float* __restrict__ bq, const float* __restrict__ bfc)
{
    int m = blockIdx.x, hc = threadIdx.x;     // grid 64, block 256
    float s = 0.0f;
    for (int o = 0; o < 128; o++)
        s = fmaf(Wq[m * 384 + 256 + o], Wfc[o * 256 + hc], s);
    g_Wqh[m * 256 + hc] = s;
    if (hc == 0) {
        float s2 = bq[m];
        for (int o = 0; o < 128; o++)
            s2 = fmaf(Wq[m * 384 + 256 + o], bfc[o], s2);
        g_bqe[m] = s2;
    }
}

// ================= prep2: fold A, Bh, biases; misc layouts =================
__global__ void prep2_kernel(const float* __restrict__ Wz, const float* __restrict__ Wzp,
                             const float* __restrict__ Wq,
                             const float* __restrict__ Wi, const float* __restrict__ bi,
                             const float* __restrict__ Wf, const float* __restrict__ bf,
                             const float* __restrict__ Wo, const float* __restrict__ bo,
                             const float* __restrict__ Wc, const float* __restrict__ bc,
                             const float* __restrict__ Wfc)
{
    int k = blockIdx.x, h = threadIdx.x;      // grid KPAD(272), block 256
    if (k < 256) {
        float4 a = make_float4(0.f, 0.f, 0.f, 0.f);
        float4 bh;
        bh.x = Wi[h * 320 + 64 + k];
        bh.y = Wf[h * 320 + 64 + k];
        bh.z = Wo[h * 320 + 64 + k];
        bh.w = Wc[h * 320 + 64 + k];
        for (int m = 0; m < 64; m++) {
            float q  = Wq[m * 384 + k];
            float qh = g_Wqh[m * 256 + k];
            float wi = Wi[h * 320 + m], wf = Wf[h * 320 + m];
            float wo = Wo[h * 320 + m], wc = Wc[h * 320 + m];
            a.x = fmaf(wi, q, a.x);  a.y = fmaf(wf, q, a.y);
            a.z = fmaf(wo, q, a.z);  a.w = fmaf(wc, q, a.w);
            bh.x = fmaf(wi, qh, bh.x); bh.y = fmaf(wf, qh, bh.y);
            bh.z = fmaf(wo, qh, bh.z); bh.w = fmaf(wc, qh, bh.w);
        }
        g_A4 [k * 256 + h] = a;
        g_Bh4[k * 256 + h] = bh;
    } else {
        float4 zz = make_float4(0.f, 0.f, 0.f, 0.f);
        g_A4 [k * 256 + h] = zz;
        g_Bh4[k * 256 + h] = zz;
    }
    if (k == 0) {
        float4 b4 = make_float4(bi[h], bf[h], bo[h], bc[h]);
        for (int m = 0; m < 64; m++) {
            float e = g_bqe[m];
            b4.x = fmaf(Wi[h * 320 + m], e, b4.x);
            b4.y = fmaf(Wf[h * 320 + m], e, b4.y);
            b4.z = fmaf(Wo[h * 320 + m], e, b4.z);
            b4.w = fmaf(Wc[h * 320 + m], e, b4.w);
        }
        g_bias4[h] = b4;
    }
    if (k == 1 && h < 128) {
        g_wzd[h]  = Wz[h * 128 + h];
        g_wzpd[h] = Wzp[h * 128 + h];
    }
    if (k < 128 && h < 128)   // WfcT2[hp=k][o=h]
        g_WfcT2[k * 128 + h] = make_float2(Wfc[h * 256 + 2 * k], Wfc[h * 256 + 2 * k + 1]);
}

// ================= G precompute: G = A @ [z,zp] + bias, all (b,t) in parallel ==========
__global__ __launch_bounds__(NTHR) void gpre_kernel(
    const float* __restrict__ inp, const float* __restrict__ xmean,
    const float* __restrict__ bz,  const float* __restrict__ bzp)
{
    __shared__ __align__(16) u64 u2dup[RPP * 256];   // 32 KB, (v,v) duplicated
    __shared__ float s_wzd[128], s_bz[128], s_wzpd[128], s_bzp[128];

    const int tid = threadIdx.x;
    const int bt0 = blockIdx.x * RPP;                 // grid = BT/RPP = 3200

    if (tid < 128) {
        s_wzd[tid] = g_wzd[tid];   s_bz[tid]  = bz[tid];
        s_wzpd[tid] = g_wzpd[tid]; s_bzp[tid] = bzp[tid];
    }
    __syncthreads();

    const long cs = (long)Tt * Dd;
    for (int e = tid; e < RPP * 128; e += NTHR) {
        int row = e >> 7, j = e & 127;
        int bt = bt0 + row, b = bt / Tt, t = bt - b * Tt;
        long base = ((long)b * 6 * Tt + t) * (long)Dd + j;
        float x   = inp[base];
        float xl  = inp[base + 1 * cs];
        float mk  = inp[base + 2 * cs];
        float dl  = inp[base + 3 * cs];
        float xlb = inp[base + 4 * cs];
        float dlb = inp[base + 5 * cs];
        float xm  = xmean[((long)b * Tt + t) * (long)Dd + j];
        float dz  = __expf(-fmaxf(fmaf(dl,  s_wzd[j],  s_bz[j]),  0.0f));
        float dzp = __expf(-fmaxf(fmaf(dlb, s_wzpd[j], s_bzp[j]), 0.0f));
        float z   = mk * x + (1.0f - mk) * (dz  * xl  + (1.0f - dz)  * xm);
        float zp  = mk * x + (1.0f - mk) * (dzp * xlb + (1.0f - dzp) * xm);
        u2dup[row * 256 + j]       = dup2(z);
        u2dup[row * 256 + 128 + j] = dup2(zp);
    }
    __syncthreads();

    u64 aif[RPP], aoc[RPP];
    {
        float4 b4 = g_bias4[tid];
#pragma unroll
        for (int r = 0; r < RPP; r++) { aif[r] = pack2(b4.x, b4.y); aoc[r] = pack2(b4.z, b4.w); }
    }
    const ulonglong2* __restrict__ wg = reinterpret_cast<const ulonglong2*>(g_A4) + tid;
    ulonglong2 wb[8];
#pragma unroll
    for (int i = 0; i < 8; i++) wb[i] = ldcg_v2(wg + i * 256);
#pragma unroll 1
    for (int k0 = 0; k0 < 256; k0 += 8) {
#pragma unroll
        for (int i = 0; i < 8; i += 2) {
            ulonglong2 w0 = wb[i], w1 = wb[i + 1];
            wb[i]     = ldcg_v2(wg + (k0 + 8 + i) * 256);
            wb[i + 1] = ldcg_v2(wg + (k0 + 9 + i) * 256);
#pragma unroll
            for (int r = 0; r < RPP; r++) {
                ulonglong2 hh = *reinterpret_cast<const ulonglong2*>(&u2dup[r * 256 + k0 + i]);
                fma2(aif[r], w0.x, hh.x); fma2(aoc[r], w0.y, hh.x);
                fma2(aif[r], w1.x, hh.y); fma2(aoc[r], w1.y, hh.y);
            }
        }
    }
#pragma unroll
    for (int r = 0; r < RPP; r++) {
        float gi, gf, go, gc;
        unpack2(aif[r], gi, gf); unpack2(aoc[r], go, gc);
        g_G4[(long)(bt0 + r) * 256 + tid] = make_float4(gi, gf, go, gc);
    }
}

// ================= scan: 128 persistent CTAs, weights SMEM-resident =================
// CTA (rg, hg): rows [rg*32, rg*32+32), h-cols [hg*16, hg*16+16).
// 512 threads GEMM: tid = kg(2b)|rq(3b)|hcol(4b); kg covers 64 k's, rq covers 4 rows.
// Reduce: thread owns output (row = tid>>4, hc = tid&15); c-state in register.
// h exchange via g_Hex (double-buffered) + per-(rg,hg) release/acquire flags.
__global__ __launch_bounds__(STH, 1) void scan_kernel()
{
    extern __shared__ __align__(16) char smraw[];
    ulonglong2* ws   = reinterpret_cast<ulonglong2*>(smraw);                // [256][16]   65536 B
    u64*        hdup = reinterpret_cast<u64*>(smraw + 65536);               // [32][HSTR]  66560 B
    ulonglong2* part = reinterpret_cast<ulonglong2*>(smraw + 65536 + 32 * HSTR * 8); // [4][32][16] 16384 B

    const int tid = threadIdx.x;
    const int rg  = blockIdx.x >> 4;
    const int hg  = blockIdx.x & 15;
    const int kg  = tid >> 7;
    const int rq  = (tid >> 4) & 7;
    const int hcol = tid & 15;
    const int kb  = kg << 6;

    // resident weight slice: ws[k][hc] = Bh4[k][hg*16+hc] (as 2 packed u64 lanes)
    {
        const ulonglong2* w2g = reinterpret_cast<const ulonglong2*>(g_Bh4);
        for (int i = tid; i < 256 * 16; i += STH) {
            int k = i >> 4, hc = i & 15;
            ws[i] = w2g[k * 256 + hg * 16 + hc];
        }
    }

    // reduce-stage identity
    const int rrow = tid >> 4;                 // 0..31
    const int rh   = tid & 15;
    const int gb   = rg * ROWS_PC + rrow;      // global batch row
    const int ghh  = hg * HC_PC + rh;          // global h
    float c_reg = 0.0f;
    float4 gv = g_G4[(long)gb * Tt * 256 + ghh];   // G for t=0

    int* const flagp = g_flag + rg * 16;
    const int slotF = 8 * 16 * (ROWS_PC * HC_PC);
    __syncthreads();

    for (int t = 0; t < Tt; t++) {
        // ---- 1. wait: all 16 h-group peers of this row-group published h_{t-1} ----
        if (tid < 16) {
            int v;
            do {
                asm volatile("ld.acquire.gpu.global.s32 %0, [%1];" : "=r"(v) : "l"(flagp + tid));
            } while (v < t);
        }
        __syncthreads();

        // ---- 2. stage h_prev[32 rows][256] into SMEM, duplicated (v,v) ----
        {
            const int prv = (t & 1) ^ 1;
            const float* src = g_Hex + prv * slotF + rg * (16 * ROWS_PC * HC_PC);
#pragma unroll
            for (int i = 0; i < 8192 / STH; i++) {
                int e = tid + i * STH;
                float v = __ldcg(src + e);
                int k   = ((e >> 9) << 4) | (e & 15);
                int row = (e >> 4) & 31;
                hdup[row * HSTR + k] = dup2(v);
            }
        }
        __syncthreads();

        // ---- 3. GEMM: 64 k x 4 rows x 1 hcol, weights from SMEM ----
        u64 aif[4], aoc[4];
#pragma unroll
        for (int j = 0; j < 4; j++) { aif[j] = 0ull; aoc[j] = 0ull; }
        {
            const ulonglong2* wp = ws + hcol;
            const u64* hbase = hdup + (rq * 4) * HSTR;
#pragma unroll 4
            for (int k0 = kb; k0 < kb + 64; k0 += 4) {
                ulonglong2 w0 = wp[(k0 + 0) * 16];
                ulonglong2 w1 = wp[(k0 + 1) * 16];
                ulonglong2 w2v = wp[(k0 + 2) * 16];
                ulonglong2 w3 = wp[(k0 + 3) * 16];
#pragma unroll
                for (int j = 0; j < 4; j++) {
                    ulonglong2 ha = *reinterpret_cast<const ulonglong2*>(hbase + j * HSTR + k0);
                    ulonglong2 hb = *reinterpret_cast<const ulonglong2*>(hbase + j * HSTR + k0 + 2);
                    fma2(aif[j], w0.x, ha.x); fma2(aoc[j], w0.y, ha.x);
                    fma2(aif[j], w1.x, ha.y); fma2(aoc[j], w1.y, ha.y);
                    fma2(aif[j], w2v.x, hb.x); fma2(aoc[j], w2v.y, hb.x);
                    fma2(aif[j], w3.x, hb.y); fma2(aoc[j], w3.y, hb.y);
                }
            }
        }
        // ---- 4. deposit k-group partials ----
#pragma unroll
        for (int j = 0; j < 4; j++) {
            ulonglong2 p; p.x = aif[j]; p.y = aoc[j];
            part[(kg * 32 + rq * 4 + j) * 16 + hcol] = p;
        }
        __syncthreads();

        // ---- 5. reduce + activations + publish ----
        {
            ulonglong2 p0 = part[(0 * 32 + rrow) * 16 + rh];
            ulonglong2 p1 = part[(1 * 32 + rrow) * 16 + rh];
            ulonglong2 p2 = part[(2 * 32 + rrow) * 16 + rh];
            ulonglong2 p3 = part[(3 * 32 + rrow) * 16 + rh];
            u64 tif = add2(add2(p0.x, p1.x), add2(p2.x, p3.x));
            u64 toc = add2(add2(p0.y, p1.y), add2(p2.y, p3.y));
            tif = add2(tif, pack2(gv.x, gv.y));
            toc = add2(toc, pack2(gv.z, gv.w));
            float ai, afv, ao, ac;
            unpack2(tif, ai, afv); unpack2(toc, ao, ac);
            float ig = fast_sigmoid(ai), fg = fast_sigmoid(afv);
            float og = fast_sigmoid(ao), ct = fast_tanh(ac);
            c_reg = fg * c_reg + ig * ct;
            float hv = og * fast_tanh(c_reg);

            const int cur = t & 1;
            g_Hex[cur * slotF + ((rg * 16 + hg) * (ROWS_PC * HC_PC)) + rrow * 16 + rh] = hv;
            g_H[((long)gb * Tt + t) * 256 + ghh] = hv;
            if (t + 1 < Tt) gv = g_G4[((long)gb * Tt + t + 1) * 256 + ghh];  // prefetch next G
        }
        __syncthreads();
        if (tid == 0) {
            asm volatile("fence.acq_rel.gpu;" ::: "memory");
            asm volatile("st.relaxed.gpu.global.s32 [%0], %1;" :: "l"(flagp + hg), "r"(t + 1) : "memory");
        }
    }
}

// ================= epilogue: out = H @ Wfc^T + bfc (fully parallel) =================
__global__ __launch_bounds__(NTHR) void epi_kernel(const float* __restrict__ bfc,
                                                   float* __restrict__ out)
{
    __shared__ __align__(16) float hs[EROWS * 256];   // 32 KB
    const int tid = threadIdx.x;
    const int bt0 = blockIdx.x * EROWS;               // grid = BT/EROWS = 1600

    for (int e = tid; e < EROWS * 256; e += NTHR)
        hs[e] = g_H[(long)bt0 * 256 + e];
    __syncthreads();

    const int o  = tid & 127;
    const int rb = (tid >> 7) * 16;                   // rows rb .. rb+15
    u64 acc[16];
#pragma unroll
    for (int r = 0; r < 16; r++) acc[r] = 0ull;

    const u64* __restrict__ w2 = reinterpret_cast<const u64*>(g_WfcT2) + o;
#pragma unroll 4
    for (int hpi = 0; hpi < 128; hpi++) {
        u64 w = w2[hpi * 128];
#pragma unroll
        for (int r = 0; r < 16; r++)
            fma2(acc[r], w, *reinterpret_cast<const u64*>(&hs[(rb + r) * 256 + 2 * hpi]));
    }
    const float bo_ = bfc[o];
#pragma unroll
    for (int r = 0; r < 16; r++) {
        float x0, x1; unpack2(acc[r], x0, x1);
        out[(long)(bt0 + rb + r) * Oo + o] = bo_ + x0 + x1;
    }
}

// ================= launch =================
#define SCAN_SMEM (65536 + 32*HSTR*8 + 4*32*16*16)   // 65536 + 66560 + 16384 = 148480

extern "C" void kernel_launch(void* const* d_in, const int* in_sizes, int n_in,
                              void* d_out, int out_size)
{
    const float* inp   = (const float*)d_in[0];
    const float* xmean = (const float*)d_in[1];
    const float* Wz    = (const float*)d_in[2];
    const float* bz    = (const float*)d_in[3];
    const float* Wzp   = (const float*)d_in[4];
    const float* bzp   = (const float*)d_in[5];
    const float* Wq    = (const float*)d_in[6];
    const float* bq    = (const float*)d_in[7];
    const float* Wi    = (const float*)d_in[8];
    const float* bi    = (const float*)d_in[9];
    const float* Wf    = (const float*)d_in[10];
    const float* bf    = (const float*)d_in[11];
    const float* Wo    = (const float*)d_in[12];
    const float* bo    = (const float*)d_in[13];
    const float* Wc    = (const float*)d_in[14];
    const float* bc    = (const float*)d_in[15];
    const float* Wfc   = (const float*)d_in[16];
    const float* bfc   = (const float*)d_in[17];
    float* out = (float*)d_out;

    cudaFuncSetAttribute(scan_kernel, cudaFuncAttributeMaxDynamicSharedMemorySize, SCAN_SMEM);

    reset_kernel<<<256, 256>>>();
    prep1_kernel<<<64, 256>>>(Wq, Wfc, bq, bfc);
    prep2_kernel<<<KPAD, 256>>>(Wz, Wzp, Wq, Wi, bi, Wf, bf, Wo, bo, Wc, bc, Wfc);
    gpre_kernel<<<BT / RPP, NTHR>>>(inp, xmean, bz, bzp);
    scan_kernel<<<SCTA, STH, SCAN_SMEM>>>();
    epi_kernel<<<BT / EROWS, NTHR>>>(bfc, out);
}